// round 7
// baseline (speedup 1.0000x reference)
#include <cuda_runtime.h>
#include <cuda_fp16.h>
#include <cstdint>

#define DI __device__ __forceinline__

// ---------------- problem sizes ----------------
static constexpr int M = 8192;
static constexpr int N = 4096;
static constexpr int K = 4096;

// ---------------- GEMM tiling: dual-pipe CTA 192x128, K-chunk 64 ----------------
static constexpr int BM_H = 128;                // HMMA rows per CTA
static constexpr int BM_I = 64;                 // IMMA rows per CTA
static constexpr int BM   = BM_H + BM_I;        // 192
static constexpr int BN   = 128;
static constexpr int KC   = 64;                 // K elements per chunk
static constexpr int NCHUNK = K / KC;           // 64
static constexpr int MT = (M + BM - 1) / BM;    // 43 m-tiles (last partial)
static constexpr int M_PAD = MT * BM;           // 8256

static constexpr int PITCH16 = 144;             // 128B fp16 row + 16B pad (9x16 -> conflict-free)
static constexpr int PITCH8  = 80;              // 64B int8 row + 16B pad  (5x16 -> conflict-free)

static constexpr int ST_A16 = 0;
static constexpr int ST_B16 = ST_A16 + BM_H * PITCH16;       // 18432
static constexpr int ST_A8  = ST_B16 + BN * PITCH16;         // 36864
static constexpr int ST_B8  = ST_A8 + BM_I * PITCH8;         // 41984
static constexpr int STAGE_BYTES = ST_B8 + BN * PITCH8;      // 52224
static constexpr int SMEM_TOTAL = 3 * STAGE_BYTES;           // 156672 -> 1 CTA/SM, 12 warps

// ---------------- device scratch ----------------
__device__ __half g_xq[(size_t)M * K];          // fp16 quantized activations (exact ints)
__device__ int8_t g_xq8[(size_t)M_PAD * K];     // int8 copy (padded rows for last tile)
__device__ __half g_wq[(size_t)N * K];          // fp16 ternary weights
__device__ int8_t g_wq8[(size_t)N * K];         // int8 ternary weights
__device__ float  g_sx[M];
__device__ double g_part[4096];
__device__ float  g_sw;
__device__ float  g_wdenom;

// ---------------- helpers ----------------
DI uint32_t smem_u32(const void* p) {
    uint32_t a;
    asm("{ .reg .u64 t; cvta.to.shared.u64 t, %1; cvt.u32.u64 %0, t; }" : "=r"(a) : "l"(p));
    return a;
}
DI void cp16(uint32_t dst, const void* src) {
    asm volatile("cp.async.cg.shared.global [%0], [%1], 16;"
                 :: "r"(dst), "l"(__cvta_generic_to_global(src)) : "memory");
}
DI void cp_commit() { asm volatile("cp.async.commit_group;" ::: "memory"); }
DI void cp_wait1()  { asm volatile("cp.async.wait_group 1;"  ::: "memory"); }

DI void ldsm_x4(uint32_t* r, uint32_t addr) {
    asm volatile("ldmatrix.sync.aligned.m8n8.x4.shared.b16 {%0,%1,%2,%3}, [%4];"
                 : "=r"(r[0]), "=r"(r[1]), "=r"(r[2]), "=r"(r[3]) : "r"(addr));
}
DI void hmma(float* c, const uint32_t* a, uint32_t b0, uint32_t b1) {
    asm volatile(
        "mma.sync.aligned.m16n8k16.row.col.f32.f16.f16.f32 "
        "{%0,%1,%2,%3}, {%4,%5,%6,%7}, {%8,%9}, {%0,%1,%2,%3};"
        : "+f"(c[0]), "+f"(c[1]), "+f"(c[2]), "+f"(c[3])
        : "r"(a[0]), "r"(a[1]), "r"(a[2]), "r"(a[3]), "r"(b0), "r"(b1));
}
DI void imma(int* c, const uint32_t* a, uint32_t b0, uint32_t b1) {
    asm volatile(
        "mma.sync.aligned.m16n8k32.row.col.s32.s8.s8.s32 "
        "{%0,%1,%2,%3}, {%4,%5,%6,%7}, {%8,%9}, {%0,%1,%2,%3};"
        : "+r"(c[0]), "+r"(c[1]), "+r"(c[2]), "+r"(c[3])
        : "r"(a[0]), "r"(a[1]), "r"(a[2]), "r"(a[3]), "r"(b0), "r"(b1));
}
DI uint32_t pack_h2(float a, float b) {
    __half2 t = __floats2half2_rn(a, b);
    return *reinterpret_cast<uint32_t*>(&t);
}
DI uint32_t pack_i8(float a, float b, float c, float d) {
    return ((uint32_t)(uint8_t)(int8_t)(int)a) |
           ((uint32_t)(uint8_t)(int8_t)(int)b << 8) |
           ((uint32_t)(uint8_t)(int8_t)(int)c << 16) |
           ((uint32_t)(uint8_t)(int8_t)(int)d << 24);
}

// ==================== quantization ====================

__global__ void k_wabs(const float* __restrict__ w) {
    __shared__ double red[256];
    const int row = blockIdx.x;
    const float4* p = reinterpret_cast<const float4*>(w + (size_t)row * 4096);
    double s = 0.0;
#pragma unroll
    for (int j = 0; j < 4; ++j) {
        float4 v = p[threadIdx.x + j * 256];
        s += (double)fabsf(v.x) + (double)fabsf(v.y) + (double)fabsf(v.z) + (double)fabsf(v.w);
    }
    red[threadIdx.x] = s;
    __syncthreads();
    for (int st = 128; st > 0; st >>= 1) {
        if (threadIdx.x < st) red[threadIdx.x] += red[threadIdx.x + st];
        __syncthreads();
    }
    if (threadIdx.x == 0) g_part[row] = red[0];
}

__global__ void k_wscale() {
    __shared__ double red[256];
    double s = 0.0;
#pragma unroll
    for (int j = 0; j < 16; ++j) s += g_part[threadIdx.x + j * 256];
    red[threadIdx.x] = s;
    __syncthreads();
    for (int st = 128; st > 0; st >>= 1) {
        if (threadIdx.x < st) red[threadIdx.x] += red[threadIdx.x + st];
        __syncthreads();
    }
    if (threadIdx.x == 0) {
        float sc = (float)(red[0] / 16777216.0);
        g_sw = sc;
        g_wdenom = sc + 1e-8f;
    }
}

__global__ void k_wq(const float* __restrict__ w) {
    const size_t i = (size_t)blockIdx.x * 256 + threadIdx.x;   // float4 index
    float4 v = reinterpret_cast<const float4*>(w)[i];
    const float d = g_wdenom;
    float q0 = fminf(fmaxf(rintf(v.x / d), -1.f), 1.f);
    float q1 = fminf(fmaxf(rintf(v.y / d), -1.f), 1.f);
    float q2 = fminf(fmaxf(rintf(v.z / d), -1.f), 1.f);
    float q3 = fminf(fmaxf(rintf(v.w / d), -1.f), 1.f);
    uint2 o;
    o.x = pack_h2(q0, q1);
    o.y = pack_h2(q2, q3);
    reinterpret_cast<uint2*>(g_wq)[i] = o;
    reinterpret_cast<uint32_t*>(g_wq8)[i] = pack_i8(q0, q1, q2, q3);
}

__global__ void k_xq(const float* __restrict__ x) {
    __shared__ float red[256];
    __shared__ float s_scale;
    const int row = blockIdx.x;
    const float4* p = reinterpret_cast<const float4*>(x + (size_t)row * 4096);
    float4 v[4];
    float am = 0.f;
#pragma unroll
    for (int j = 0; j < 4; ++j) {
        v[j] = p[threadIdx.x + j * 256];
        am = fmaxf(am, fmaxf(fmaxf(fabsf(v[j].x), fabsf(v[j].y)),
                             fmaxf(fabsf(v[j].z), fabsf(v[j].w))));
    }
    red[threadIdx.x] = am;
    __syncthreads();
    for (int st = 128; st > 0; st >>= 1) {
        if (threadIdx.x < st) red[threadIdx.x] = fmaxf(red[threadIdx.x], red[threadIdx.x + st]);
        __syncthreads();
    }
    if (threadIdx.x == 0) {
        float sc = fmaxf(red[0] / 127.0f, 1e-8f);
        s_scale = sc;
        g_sx[row] = sc;
    }
    __syncthreads();
    const float sc = s_scale;
    uint2* out16 = reinterpret_cast<uint2*>(g_xq + (size_t)row * 4096);
    uint32_t* out8 = reinterpret_cast<uint32_t*>(g_xq8 + (size_t)row * 4096);
#pragma unroll
    for (int j = 0; j < 4; ++j) {
        float q0 = fminf(fmaxf(rintf(v[j].x / sc), -127.f), 127.f);
        float q1 = fminf(fmaxf(rintf(v[j].y / sc), -127.f), 127.f);
        float q2 = fminf(fmaxf(rintf(v[j].z / sc), -127.f), 127.f);
        float q3 = fminf(fmaxf(rintf(v[j].w / sc), -127.f), 127.f);
        uint2 o;
        o.x = pack_h2(q0, q1);
        o.y = pack_h2(q2, q3);
        out16[threadIdx.x + j * 256] = o;
        out8[threadIdx.x + j * 256] = pack_i8(q0, q1, q2, q3);
    }
}

// ==================== dual-pipe GEMM ====================
// CTA tile 192x128: warps 0-7 HMMA on rows 0-127 (64x32 warp tiles, 2m x 4n),
// warps 8-11 IMMA/dp4a on rows 128-191 (32x64 warp tiles, 2m x 2n).
// SMSP w: warps {w, w+4} HMMA + warp {w+8} IMMA -> tensor + alu pipes concurrent.

__global__ void __launch_bounds__(384, 1) k_gemm(float* __restrict__ out) {
    extern __shared__ char smem[];
    const uint32_t sb = smem_u32(smem);
    const int tid = threadIdx.x, wid = tid >> 5, lane = tid & 31;

    const int nt = blockIdx.x & 31;             // 32 n-tiles
    const int mt = blockIdx.x >> 5;             // 43 m-tiles

    const char* gA16 = (const char*)g_xq  + (size_t)mt * BM * K * 2;
    const char* gB16 = (const char*)g_wq  + (size_t)nt * BN * K * 2;
    const char* gA8  = (const char*)g_xq8 + ((size_t)mt * BM + BM_H) * K;
    const char* gB8  = (const char*)g_wq8 + (size_t)nt * BN * K;

    auto load_stage = [&](int stage, int kc) {
        const uint32_t base = sb + stage * STAGE_BYTES;
        // A16: 128 rows x 128B = 1024 segs
#pragma unroll
        for (int i = 0; i < 3; ++i) {
            const int idx = tid + i * 384;
            if (idx < 1024) {
                const int r = idx >> 3, c = idx & 7;
                cp16(base + ST_A16 + r * PITCH16 + c * 16,
                     gA16 + (size_t)r * 8192 + (size_t)kc * 128 + c * 16);
            }
        }
        // B16: 128 rows x 128B = 1024 segs
#pragma unroll
        for (int i = 0; i < 3; ++i) {
            const int idx = tid + i * 384;
            if (idx < 1024) {
                const int r = idx >> 3, c = idx & 7;
                cp16(base + ST_B16 + r * PITCH16 + c * 16,
                     gB16 + (size_t)r * 8192 + (size_t)kc * 128 + c * 16);
            }
        }
        // A8: 64 rows x 64B = 256 segs
        if (tid < 256) {
            const int r = tid >> 2, c = tid & 3;
            cp16(base + ST_A8 + r * PITCH8 + c * 16,
                 gA8 + (size_t)r * 4096 + (size_t)kc * 64 + c * 16);
        }
        // B8: 128 rows x 64B = 512 segs
#pragma unroll
        for (int i = 0; i < 2; ++i) {
            const int idx = tid + i * 384;
            if (idx < 512) {
                const int r = idx >> 2, c = idx & 3;
                cp16(base + ST_B8 + r * PITCH8 + c * 16,
                     gB8 + (size_t)r * 4096 + (size_t)kc * 64 + c * 16);
            }
        }
    };

    // ---- per-warp fragment addressing ----
    // HMMA (wid 0-7)
    const int wm = wid & 1, wn = wid >> 1;            // 2m x 4n
    const int rowL = lane & 15, byteL = (lane >> 4) * 16;
    uint32_t aoff[4], boff[2];
#pragma unroll
    for (int im = 0; im < 4; ++im)
        aoff[im] = (uint32_t)(ST_A16 + (wm * 64 + im * 16 + rowL) * PITCH16 + byteL);
#pragma unroll
    for (int ib = 0; ib < 2; ++ib)
        boff[ib] = (uint32_t)(ST_B16 + (wn * 32 + ib * 16 + rowL) * PITCH16 + byteL);

    // IMMA (wid 8-11)
    const int wi = wid - 8;
    const int im_m = wi & 1, im_n = wi >> 1;          // 2m x 2n
    const int rowL8 = ((lane >> 3) & 1) * 8 + (lane & 7);
    const int byteL8 = (lane >> 4) * 16;
    uint32_t a8off[2], b8off[4];
#pragma unroll
    for (int im = 0; im < 2; ++im)
        a8off[im] = (uint32_t)(ST_A8 + (im_m * 32 + im * 16 + rowL8) * PITCH8 + byteL8);
#pragma unroll
    for (int ib = 0; ib < 4; ++ib)
        b8off[ib] = (uint32_t)(ST_B8 + (im_n * 64 + ib * 16 + rowL8) * PITCH8 + byteL8);

    float facc[4][4][4];
    int   iacc[2][8][4];
#pragma unroll
    for (int i = 0; i < 4; ++i)
#pragma unroll
        for (int j = 0; j < 4; ++j)
#pragma unroll
            for (int q = 0; q < 4; ++q) facc[i][j][q] = 0.f;
#pragma unroll
    for (int i = 0; i < 2; ++i)
#pragma unroll
        for (int j = 0; j < 8; ++j)
#pragma unroll
            for (int q = 0; q < 4; ++q) iacc[i][j][q] = 0;

    load_stage(0, 0); cp_commit();
    load_stage(1, 1); cp_commit();

    int rd = 0, wr = 2;
    for (int kc = 0; kc < NCHUNK; ++kc) {
        cp_wait1();
        __syncthreads();

        if (kc + 2 < NCHUNK) load_stage(wr, kc + 2);
        cp_commit();

        const uint32_t base = sb + rd * STAGE_BYTES;
        if (wid < 8) {
            // HMMA path: 4 k16 steps
#pragma unroll
            for (int ks = 0; ks < 4; ++ks) {
                uint32_t a[4][4], b[2][4];
#pragma unroll
                for (int im = 0; im < 4; ++im) ldsm_x4(a[im], base + aoff[im] + ks * 32);
#pragma unroll
                for (int ib = 0; ib < 2; ++ib) ldsm_x4(b[ib], base + boff[ib] + ks * 32);
#pragma unroll
                for (int im = 0; im < 4; ++im) {
#pragma unroll
                    for (int in = 0; in < 4; ++in) {
                        const int ib = in >> 1, od = in & 1;
                        hmma(facc[im][in], a[im], b[ib][od ? 1 : 0], b[ib][od ? 3 : 2]);
                    }
                }
            }
        } else {
            // IMMA path: 2 k32 steps
#pragma unroll
            for (int ks = 0; ks < 2; ++ks) {
                uint32_t a[2][4], b[4][4];
#pragma unroll
                for (int im = 0; im < 2; ++im) ldsm_x4(a[im], base + a8off[im] + ks * 32);
#pragma unroll
                for (int ib = 0; ib < 4; ++ib) ldsm_x4(b[ib], base + b8off[ib] + ks * 32);
#pragma unroll
                for (int im = 0; im < 2; ++im) {
#pragma unroll
                    for (int in = 0; in < 8; ++in) {
                        const int ib = in >> 1, od = in & 1;
                        imma(iacc[im][in], a[im], b[ib][od ? 1 : 0], b[ib][od ? 3 : 2]);
                    }
                }
            }
        }
        rd = (rd == 2) ? 0 : rd + 1;
        wr = (wr == 2) ? 0 : wr + 1;
    }

    // ---- epilogue ----
    const float swv = g_sw;
    if (wid < 8) {
        const int row0 = mt * BM + wm * 64 + (lane >> 2);           // always < M
        const int col0 = nt * BN + wn * 32 + 2 * (lane & 3);
#pragma unroll
        for (int im = 0; im < 4; ++im) {
            const int r = row0 + im * 16;
            const float f0 = g_sx[r] * swv;
            const float f8 = g_sx[r + 8] * swv;
            float* po0 = out + (size_t)r * N + col0;
            float* po8 = out + (size_t)(r + 8) * N + col0;
#pragma unroll
            for (int in = 0; in < 4; ++in) {
                float2 v0, v8;
                v0.x = facc[im][in][0] * f0;
                v0.y = facc[im][in][1] * f0;
                v8.x = facc[im][in][2] * f8;
                v8.y = facc[im][in][3] * f8;
                *reinterpret_cast<float2*>(po0 + in * 8) = v0;
                *reinterpret_cast<float2*>(po8 + in * 8) = v8;
            }
        }
    } else {
        const int row0 = mt * BM + BM_H + im_m * 32 + (lane >> 2);  // may exceed M on last tile
        const int col0 = nt * BN + im_n * 64 + 2 * (lane & 3);
#pragma unroll
        for (int im = 0; im < 2; ++im) {
            const int r = row0 + im * 16;
            const float f0 = (r     < M) ? g_sx[r] * swv     : 0.f;
            const float f8 = (r + 8 < M) ? g_sx[r + 8] * swv : 0.f;
            float* po0 = out + (size_t)r * N + col0;
            float* po8 = out + (size_t)(r + 8) * N + col0;
#pragma unroll
            for (int in = 0; in < 8; ++in) {
                float2 v0, v8;
                v0.x = (float)iacc[im][in][0] * f0;
                v0.y = (float)iacc[im][in][1] * f0;
                v8.x = (float)iacc[im][in][2] * f8;
                v8.y = (float)iacc[im][in][3] * f8;
                if (r     < M) *reinterpret_cast<float2*>(po0 + in * 8) = v0;
                if (r + 8 < M) *reinterpret_cast<float2*>(po8 + in * 8) = v8;
            }
        }
    }
}

// ==================== launch ====================
extern "C" void kernel_launch(void* const* d_in, const int* in_sizes, int n_in,
                              void* d_out, int out_size) {
    const float* x = (const float*)d_in[0];
    const float* w = (const float*)d_in[1];
    float* out = (float*)d_out;
    (void)in_sizes; (void)n_in; (void)out_size;

    k_wabs<<<4096, 256>>>(w);
    k_wscale<<<1, 256>>>();
    k_wq<<<16384, 256>>>(w);
    k_xq<<<8192, 256>>>(x);

    cudaFuncSetAttribute(k_gemm, cudaFuncAttributeMaxDynamicSharedMemorySize, SMEM_TOTAL);
    k_gemm<<<MT * (N / BN), 384, SMEM_TOTAL>>>(out);
}

// round 8
// speedup vs baseline: 1.9450x; 1.9450x over previous
#include <cuda_runtime.h>
#include <cuda_fp16.h>
#include <cstdint>

#define DI __device__ __forceinline__

// ---------------- problem sizes ----------------
static constexpr int M = 8192;
static constexpr int N = 4096;
static constexpr int K = 4096;

// ---------------- GEMM tiling (R5 shape, deeper pipeline) ----------------
static constexpr int BM = 128;
static constexpr int BN = 128;
static constexpr int BKH = 32;                  // 32 halves per K-chunk = 64 B rows
static constexpr int NCHUNK = K / BKH;          // 128
static constexpr int NSTAGE = 5;
static constexpr int PITCH = 80;                // 64B row padded -> conflict-free ldmatrix
static constexpr int A_BYTES = BM * PITCH;      // 10240
static constexpr int B_BYTES = BN * PITCH;      // 10240
static constexpr int STAGE_BYTES = A_BYTES + B_BYTES;        // 20480
static constexpr int SMEM_TOTAL = NSTAGE * STAGE_BYTES;      // 102400 -> 2 CTAs/SM

// ---------------- device scratch ----------------
__device__ __half g_xq[(size_t)M * K];          // 64 MB quantized activations (exact ints)
__device__ __half g_wq[(size_t)N * K];          // 32 MB ternary weights {-1,0,1}
__device__ float  g_sx[M];
__device__ double g_part[4096];
__device__ float  g_sw;
__device__ float  g_wdenom;

// ---------------- helpers ----------------
DI uint32_t smem_u32(const void* p) {
    uint32_t a;
    asm("{ .reg .u64 t; cvta.to.shared.u64 t, %1; cvt.u32.u64 %0, t; }" : "=r"(a) : "l"(p));
    return a;
}
DI void cp16(uint32_t dst, const void* src) {
    asm volatile("cp.async.cg.shared.global [%0], [%1], 16;"
                 :: "r"(dst), "l"(__cvta_generic_to_global(src)) : "memory");
}
DI void cp_commit() { asm volatile("cp.async.commit_group;" ::: "memory"); }
DI void cp_wait3()  { asm volatile("cp.async.wait_group 3;"  ::: "memory"); }

DI void ldsm_x4(uint32_t* r, uint32_t addr) {
    asm volatile("ldmatrix.sync.aligned.m8n8.x4.shared.b16 {%0,%1,%2,%3}, [%4];"
                 : "=r"(r[0]), "=r"(r[1]), "=r"(r[2]), "=r"(r[3]) : "r"(addr));
}
DI void hmma(float* c, const uint32_t* a, uint32_t b0, uint32_t b1) {
    asm volatile(
        "mma.sync.aligned.m16n8k16.row.col.f32.f16.f16.f32 "
        "{%0,%1,%2,%3}, {%4,%5,%6,%7}, {%8,%9}, {%0,%1,%2,%3};"
        : "+f"(c[0]), "+f"(c[1]), "+f"(c[2]), "+f"(c[3])
        : "r"(a[0]), "r"(a[1]), "r"(a[2]), "r"(a[3]), "r"(b0), "r"(b1));
}
DI uint32_t pack_h2(float a, float b) {
    __half2 t = __floats2half2_rn(a, b);
    return *reinterpret_cast<uint32_t*>(&t);
}

// ==================== quantization ====================

__global__ void k_wabs(const float* __restrict__ w) {
    __shared__ double red[256];
    const int row = blockIdx.x;
    const float4* p = reinterpret_cast<const float4*>(w + (size_t)row * 4096);
    double s = 0.0;
#pragma unroll
    for (int j = 0; j < 4; ++j) {
        float4 v = p[threadIdx.x + j * 256];
        s += (double)fabsf(v.x) + (double)fabsf(v.y) + (double)fabsf(v.z) + (double)fabsf(v.w);
    }
    red[threadIdx.x] = s;
    __syncthreads();
    for (int st = 128; st > 0; st >>= 1) {
        if (threadIdx.x < st) red[threadIdx.x] += red[threadIdx.x + st];
        __syncthreads();
    }
    if (threadIdx.x == 0) g_part[row] = red[0];
}

__global__ void k_wscale() {
    __shared__ double red[256];
    double s = 0.0;
#pragma unroll
    for (int j = 0; j < 16; ++j) s += g_part[threadIdx.x + j * 256];
    red[threadIdx.x] = s;
    __syncthreads();
    for (int st = 128; st > 0; st >>= 1) {
        if (threadIdx.x < st) red[threadIdx.x] += red[threadIdx.x + st];
        __syncthreads();
    }
    if (threadIdx.x == 0) {
        float sc = (float)(red[0] / 16777216.0);
        g_sw = sc;
        g_wdenom = sc + 1e-8f;
    }
}

__global__ void k_wq(const float* __restrict__ w) {
    const size_t i = (size_t)blockIdx.x * 256 + threadIdx.x;
    float4 v = reinterpret_cast<const float4*>(w)[i];
    const float d = g_wdenom;
    float q0 = fminf(fmaxf(rintf(v.x / d), -1.f), 1.f);
    float q1 = fminf(fmaxf(rintf(v.y / d), -1.f), 1.f);
    float q2 = fminf(fmaxf(rintf(v.z / d), -1.f), 1.f);
    float q3 = fminf(fmaxf(rintf(v.w / d), -1.f), 1.f);
    uint2 o;
    o.x = pack_h2(q0, q1);
    o.y = pack_h2(q2, q3);
    reinterpret_cast<uint2*>(g_wq)[i] = o;
}

__global__ void k_xq(const float* __restrict__ x) {
    __shared__ float red[256];
    __shared__ float s_scale;
    const int row = blockIdx.x;
    const float4* p = reinterpret_cast<const float4*>(x + (size_t)row * 4096);
    float4 v[4];
    float am = 0.f;
#pragma unroll
    for (int j = 0; j < 4; ++j) {
        v[j] = p[threadIdx.x + j * 256];
        am = fmaxf(am, fmaxf(fmaxf(fabsf(v[j].x), fabsf(v[j].y)),
                             fmaxf(fabsf(v[j].z), fabsf(v[j].w))));
    }
    red[threadIdx.x] = am;
    __syncthreads();
    for (int st = 128; st > 0; st >>= 1) {
        if (threadIdx.x < st) red[threadIdx.x] = fmaxf(red[threadIdx.x], red[threadIdx.x + st]);
        __syncthreads();
    }
    if (threadIdx.x == 0) {
        float sc = fmaxf(red[0] / 127.0f, 1e-8f);
        s_scale = sc;
        g_sx[row] = sc;
    }
    __syncthreads();
    const float sc = s_scale;
    uint2* out = reinterpret_cast<uint2*>(g_xq + (size_t)row * 4096);
#pragma unroll
    for (int j = 0; j < 4; ++j) {
        float q0 = fminf(fmaxf(rintf(v[j].x / sc), -127.f), 127.f);
        float q1 = fminf(fmaxf(rintf(v[j].y / sc), -127.f), 127.f);
        float q2 = fminf(fmaxf(rintf(v[j].z / sc), -127.f), 127.f);
        float q3 = fminf(fmaxf(rintf(v[j].w / sc), -127.f), 127.f);
        uint2 o;
        o.x = pack_h2(q0, q1);
        o.y = pack_h2(q2, q3);
        out[threadIdx.x + j * 256] = o;
    }
}

// ==================== GEMM ====================
// out[M,N] = g_xq[M,K](f16 ints) . g_wq[N,K](f16 ternary)^T, scaled by sx[m]*sw.
// CTA 128x128x32, 8 warps (2m x 4n), warp tile 64x32 via m16n8k16 HMMA, fp32 acc.
// 5-stage cp.async ring, 2 CTAs/SM (16 warps/SM, 4/SMSP).

__global__ void __launch_bounds__(256, 2) k_gemm(float* __restrict__ out) {
    extern __shared__ char smem[];
    const uint32_t sb = smem_u32(smem);
    const int tid = threadIdx.x, wid = tid >> 5, lane = tid & 31;
    const int wm = wid & 1, wn = wid >> 1;      // warp grid 2 (m) x 4 (n)

    const int nt = blockIdx.x & 31;             // n fast-varying: W stays L2-hot
    const int mt = blockIdx.x >> 5;

    const char* gA = (const char*)g_xq + (size_t)mt * BM * K * 2;
    const char* gB = (const char*)g_wq + (size_t)nt * BN * K * 2;

    // cp.async coordinates: 256 threads cover 64 rows x 64B per pass
    const int lr = tid >> 2, lc = tid & 3;

    // ldmatrix per-thread offsets
    const int rowL = lane & 15;
    const int byteL = (lane >> 4) * 16;
    uint32_t aoff[4], boff[2];
#pragma unroll
    for (int im = 0; im < 4; ++im)
        aoff[im] = (uint32_t)((wm * 64 + im * 16 + rowL) * PITCH + byteL);
#pragma unroll
    for (int ib = 0; ib < 2; ++ib)
        boff[ib] = (uint32_t)(A_BYTES + (wn * 32 + ib * 16 + rowL) * PITCH + byteL);

    float acc[4][4][4];
#pragma unroll
    for (int i = 0; i < 4; ++i)
#pragma unroll
        for (int j = 0; j < 4; ++j)
#pragma unroll
            for (int q = 0; q < 4; ++q) acc[i][j][q] = 0.f;

    auto load_stage = [&](int stage, int kc) {
        const uint32_t base = sb + stage * STAGE_BYTES;
        const size_t koff = (size_t)kc * 64;     // 64 bytes per chunk
#pragma unroll
        for (int i = 0; i < 2; ++i) {            // A: 128 rows, 8192B row stride
            const int r = lr + i * 64;
            cp16(base + r * PITCH + lc * 16, gA + (size_t)r * 8192 + koff + lc * 16);
        }
#pragma unroll
        for (int i = 0; i < 2; ++i) {            // B: 128 rows
            const int r = lr + i * 64;
            cp16(base + A_BYTES + r * PITCH + lc * 16, gB + (size_t)r * 8192 + koff + lc * 16);
        }
    };

    // prologue: stages 0..3
#pragma unroll
    for (int s = 0; s < NSTAGE - 1; ++s) { load_stage(s, s); cp_commit(); }

    int rd = 0, wr = NSTAGE - 1;
    for (int kc = 0; kc < NCHUNK; ++kc) {
        cp_wait3();
        __syncthreads();

        if (kc + NSTAGE - 1 < NCHUNK) load_stage(wr, kc + NSTAGE - 1);
        cp_commit();

        const uint32_t stage_base = sb + rd * STAGE_BYTES;
#pragma unroll
        for (int ks = 0; ks < 2; ++ks) {
            uint32_t a[4][4], b[2][4];
#pragma unroll
            for (int im = 0; im < 4; ++im) ldsm_x4(a[im], stage_base + aoff[im] + ks * 32);
#pragma unroll
            for (int ib = 0; ib < 2; ++ib) ldsm_x4(b[ib], stage_base + boff[ib] + ks * 32);
#pragma unroll
            for (int im = 0; im < 4; ++im) {
#pragma unroll
                for (int in = 0; in < 4; ++in) {
                    const int ib = in >> 1, od = in & 1;
                    hmma(acc[im][in], a[im], b[ib][od ? 1 : 0], b[ib][od ? 3 : 2]);
                }
            }
        }
        rd = (rd == NSTAGE - 1) ? 0 : rd + 1;
        wr = (wr == NSTAGE - 1) ? 0 : wr + 1;
    }

    // ---- epilogue: scale by sx[row]*sw and store ----
    const float swv = g_sw;
    const int row0 = mt * BM + wm * 64 + (lane >> 2);
    const int col0 = nt * BN + wn * 32 + 2 * (lane & 3);
#pragma unroll
    for (int im = 0; im < 4; ++im) {
        const int r = row0 + im * 16;
        const float f0 = g_sx[r] * swv;
        const float f8 = g_sx[r + 8] * swv;
        float* po0 = out + (size_t)r * N + col0;
        float* po8 = out + (size_t)(r + 8) * N + col0;
#pragma unroll
        for (int in = 0; in < 4; ++in) {
            float2 v0, v8;
            v0.x = acc[im][in][0] * f0;
            v0.y = acc[im][in][1] * f0;
            v8.x = acc[im][in][2] * f8;
            v8.y = acc[im][in][3] * f8;
            *reinterpret_cast<float2*>(po0 + in * 8) = v0;
            *reinterpret_cast<float2*>(po8 + in * 8) = v8;
        }
    }
}

// ==================== launch ====================
extern "C" void kernel_launch(void* const* d_in, const int* in_sizes, int n_in,
                              void* d_out, int out_size) {
    const float* x = (const float*)d_in[0];
    const float* w = (const float*)d_in[1];
    float* out = (float*)d_out;
    (void)in_sizes; (void)n_in; (void)out_size;

    k_wabs<<<4096, 256>>>(w);
    k_wscale<<<1, 256>>>();
    k_wq<<<16384, 256>>>(w);
    k_xq<<<8192, 256>>>(x);

    cudaFuncSetAttribute(k_gemm, cudaFuncAttributeMaxDynamicSharedMemorySize, SMEM_TOTAL);
    k_gemm<<<(M / BM) * (N / BN), 256, SMEM_TOTAL>>>(out);
}